// round 7
// baseline (speedup 1.0000x reference)
#include <cuda_runtime.h>
#include <cuda_bf16.h>
#include <math.h>
#include <stdint.h>

#define BB   2
#define SS   2048
#define DD   768
#define HH   12
#define DKK  64

#define XN 3145728   // 4096*768
#define WN 589824    // 768*768
#define HN 3145728   // BB*HH*SS*DKK
#define CN 3145728   // BB*SS*DD

// bf16 hi/lo scratch (allocation-free)
__device__ __align__(128) __nv_bfloat16 g_xhi[3 * XN];
__device__ __align__(128) __nv_bfloat16 g_xlo[3 * XN];
__device__ __align__(128) __nv_bfloat16 g_whi[4 * WN];
__device__ __align__(128) __nv_bfloat16 g_wlo[4 * WN];
__device__ __align__(128) __nv_bfloat16 g_qhi[HN];
__device__ __align__(128) __nv_bfloat16 g_qlo[HN];
__device__ __align__(128) __nv_bfloat16 g_khi[HN];
__device__ __align__(128) __nv_bfloat16 g_klo[HN];
__device__ __align__(128) __nv_bfloat16 g_vhi[HN];
__device__ __align__(128) __nv_bfloat16 g_vlo[HN];
__device__ __align__(128) __nv_bfloat16 g_chi[CN];
__device__ __align__(128) __nv_bfloat16 g_clo[CN];

// ------------------------------ helpers -------------------------------------
__device__ __forceinline__ uint32_t smem_u32(const void* p) {
    return (uint32_t)__cvta_generic_to_shared(p);
}
__device__ __forceinline__ void mma16816(float* c, const uint32_t* a,
                                         uint32_t b0, uint32_t b1) {
    asm volatile(
        "mma.sync.aligned.m16n8k16.row.col.f32.bf16.bf16.f32 "
        "{%0,%1,%2,%3}, {%4,%5,%6,%7}, {%8,%9}, {%0,%1,%2,%3};"
        : "+f"(c[0]), "+f"(c[1]), "+f"(c[2]), "+f"(c[3])
        : "r"(a[0]), "r"(a[1]), "r"(a[2]), "r"(a[3]), "r"(b0), "r"(b1));
}
__device__ __forceinline__ void ldmat4(uint32_t* r, uint32_t addr) {
    asm volatile(
        "ldmatrix.sync.aligned.m8n8.x4.shared.b16 {%0,%1,%2,%3}, [%4];"
        : "=r"(r[0]), "=r"(r[1]), "=r"(r[2]), "=r"(r[3]) : "r"(addr));
}
__device__ __forceinline__ void ldmat4t(uint32_t* r, uint32_t addr) {
    asm volatile(
        "ldmatrix.sync.aligned.m8n8.x4.trans.shared.b16 {%0,%1,%2,%3}, [%4];"
        : "=r"(r[0]), "=r"(r[1]), "=r"(r[2]), "=r"(r[3]) : "r"(addr));
}
__device__ __forceinline__ uint32_t pkbf(float a, float b) {
    __nv_bfloat162 h = __floats2bfloat162_rn(a, b);
    return *(uint32_t*)&h;
}
__device__ __forceinline__ void split2(float x, float y, uint32_t &hi, uint32_t &lo) {
    float hx = __bfloat162float(__float2bfloat16(x));
    float hy = __bfloat162float(__float2bfloat16(y));
    hi = pkbf(x, y);
    lo = pkbf(x - hx, y - hy);
}
__device__ __forceinline__ void cp16(uint32_t dst, const void* src) {
    asm volatile("cp.async.cg.shared.global [%0], [%1], 16;"
                 :: "r"(dst), "l"(src));
}
__device__ __forceinline__ void cpcommit() {
    asm volatile("cp.async.commit_group;" ::: "memory");
}
template<int N>
__device__ __forceinline__ void cpwait() {
    asm volatile("cp.async.wait_group %0;" :: "n"(N) : "memory");
}

#define SA 144   // smem row stride bytes

// ---------------------------------------------------------------------------
// Convert kernels: fp32 -> bf16 hi + lo residual
// ---------------------------------------------------------------------------
__global__ __launch_bounds__(256)
void conv_x(const float* __restrict__ x0, const float* __restrict__ x1,
            const float* __restrict__ x2)
{
    const float* src = (blockIdx.z == 0) ? x0 : (blockIdx.z == 1) ? x1 : x2;
    size_t off = (size_t)blockIdx.z * XN;
    size_t i4  = ((size_t)blockIdx.x * 256 + threadIdx.x) * 4;
    float4 v = *(const float4*)(src + i4);
    uint32_t h0, l0, h1, l1;
    split2(v.x, v.y, h0, l0);
    split2(v.z, v.w, h1, l1);
    *(uint2*)(g_xhi + off + i4) = make_uint2(h0, h1);
    *(uint2*)(g_xlo + off + i4) = make_uint2(l0, l1);
}

__global__ __launch_bounds__(256)
void conv_w(const float* __restrict__ w0, const float* __restrict__ w1,
            const float* __restrict__ w2, const float* __restrict__ w3)
{
    const float* src = (blockIdx.z == 0) ? w0 : (blockIdx.z == 1) ? w1
                     : (blockIdx.z == 2) ? w2 : w3;
    size_t off = (size_t)blockIdx.z * WN;
    size_t i4  = ((size_t)blockIdx.x * 256 + threadIdx.x) * 4;
    float4 v = *(const float4*)(src + i4);
    uint32_t h0, l0, h1, l1;
    split2(v.x, v.y, h0, l0);
    split2(v.z, v.w, h1, l1);
    *(uint2*)(g_whi + off + i4) = make_uint2(h0, h1);
    *(uint2*)(g_wlo + off + i4) = make_uint2(l0, l1);
}

// ---------------------------------------------------------------------------
// Pipelined HMMA GEMM (unchanged from R6)
// ---------------------------------------------------------------------------
#define GBUF 73728

template<int MODE>
__global__ __launch_bounds__(256)
void gemm_bf(float* __restrict__ outp)
{
    extern __shared__ char sm[];
    const uint32_t base = smem_u32(sm);

    const int tid  = threadIdx.x;
    const int warp = tid >> 5;
    const int lane = tid & 31;
    const int g    = lane >> 2;
    const int t    = lane & 3;
    const int wm   = (warp >> 2) * 64;
    const int wn   = (warp & 3) * 32;
    const int rowBase = blockIdx.y * 128;
    const int colBase = blockIdx.x * 128;
    const int z = blockIdx.z;

    const __nv_bfloat16 *Ahi, *Alo, *Bhi, *Blo;
    if (MODE == 0) {
        Ahi = g_xhi + (size_t)z * XN; Alo = g_xlo + (size_t)z * XN;
        Bhi = g_whi + (size_t)z * WN; Blo = g_wlo + (size_t)z * WN;
    } else {
        Ahi = g_chi; Alo = g_clo;
        Bhi = g_whi + (size_t)3 * WN; Blo = g_wlo + (size_t)3 * WN;
    }

    const uint32_t laneA = (uint32_t)(((lane & 7) + ((lane >> 3) & 1) * 8) * SA
                                      + (lane >> 4) * 16);
    const uint32_t laneB = (uint32_t)(((lane & 7) + ((lane >> 4) & 1) * 8) * SA
                                      + ((lane >> 3) & 1) * 16);

    float acc[4][4][4];
    #pragma unroll
    for (int mi = 0; mi < 4; ++mi)
        #pragma unroll
        for (int ni = 0; ni < 4; ++ni)
            #pragma unroll
            for (int r = 0; r < 4; ++r) acc[mi][ni][r] = 0.f;

    auto load_chunk = [&](int ch, int p) {
        const int k0 = ch * 64;
        uint32_t sb = base + p * GBUF;
        #pragma unroll
        for (int it = 0; it < 4; ++it) {
            int idx = tid + it * 256;
            int r   = idx >> 3;
            int sg  = idx & 7;
            uint32_t d = (uint32_t)(r * SA + sg * 16);
            cp16(sb +          d, Ahi + (size_t)(rowBase + r) * DD + k0 + sg * 8);
            cp16(sb + 18432u + d, Alo + (size_t)(rowBase + r) * DD + k0 + sg * 8);
            cp16(sb + 36864u + d, Bhi + (size_t)(colBase + r) * DD + k0 + sg * 8);
            cp16(sb + 55296u + d, Blo + (size_t)(colBase + r) * DD + k0 + sg * 8);
        }
    };

    load_chunk(0, 0);
    cpcommit();

    for (int ch = 0; ch < 12; ++ch) {
        if (ch < 11) { load_chunk(ch + 1, (ch + 1) & 1); cpcommit(); cpwait<1>(); }
        else         { cpwait<0>(); }
        __syncthreads();

        const uint32_t uAh = base + (ch & 1) * GBUF;
        const uint32_t uAl = uAh + 18432u;
        const uint32_t uBh = uAh + 36864u;
        const uint32_t uBl = uAh + 55296u;

        #pragma unroll
        for (int kt = 0; kt < 4; ++kt) {
            const uint32_t ko = (uint32_t)kt * 32u;
            uint32_t afh[4][4], afl[4][4];
            #pragma unroll
            for (int mi = 0; mi < 4; ++mi) {
                uint32_t ao = (uint32_t)((wm + mi * 16) * SA) + ko;
                ldmat4(afh[mi], uAh + ao + laneA);
                ldmat4(afl[mi], uAl + ao + laneA);
            }
            uint32_t bh[2][4], bl[2][4];
            #pragma unroll
            for (int np = 0; np < 2; ++np) {
                uint32_t bo = (uint32_t)((wn + np * 16) * SA) + ko;
                ldmat4(bh[np], uBh + bo + laneB);
                ldmat4(bl[np], uBl + bo + laneB);
            }
            #pragma unroll
            for (int ni = 0; ni < 4; ++ni) {
                uint32_t b0h = bh[ni >> 1][(ni & 1) * 2];
                uint32_t b1h = bh[ni >> 1][(ni & 1) * 2 + 1];
                uint32_t b0l = bl[ni >> 1][(ni & 1) * 2];
                uint32_t b1l = bl[ni >> 1][(ni & 1) * 2 + 1];
                #pragma unroll
                for (int mi = 0; mi < 4; ++mi) {
                    mma16816(acc[mi][ni], afh[mi], b0h, b1h);
                    mma16816(acc[mi][ni], afl[mi], b0h, b1h);
                    mma16816(acc[mi][ni], afh[mi], b0l, b1l);
                }
            }
        }
        __syncthreads();
    }

    const float sc = (MODE == 0 && z == 0) ? 0.125f : 1.0f;
    #pragma unroll
    for (int mi = 0; mi < 4; ++mi) {
        int r0 = rowBase + wm + mi * 16 + g;
        int r1 = r0 + 8;
        #pragma unroll
        for (int ni = 0; ni < 4; ++ni) {
            int col = colBase + wn + ni * 8 + 2 * t;
            if (MODE == 0) {
                __nv_bfloat16* dhi = (z == 0) ? g_qhi : (z == 1) ? g_khi : g_vhi;
                __nv_bfloat16* dlo = (z == 0) ? g_qlo : (z == 1) ? g_klo : g_vlo;
                int h = col >> 6, dk = col & 63;
                int b0 = r0 >> 11, s0 = r0 & (SS - 1);
                int b1 = r1 >> 11, s1 = r1 & (SS - 1);
                size_t i0 = (((size_t)b0 * HH + h) * SS + s0) * DKK + dk;
                size_t i1 = (((size_t)b1 * HH + h) * SS + s1) * DKK + dk;
                uint32_t hi, lo;
                split2(acc[mi][ni][0] * sc, acc[mi][ni][1] * sc, hi, lo);
                *(uint32_t*)(dhi + i0) = hi;
                *(uint32_t*)(dlo + i0) = lo;
                split2(acc[mi][ni][2] * sc, acc[mi][ni][3] * sc, hi, lo);
                *(uint32_t*)(dhi + i1) = hi;
                *(uint32_t*)(dlo + i1) = lo;
            } else {
                *(float2*)(outp + (size_t)r0 * DD + col) =
                    make_float2(acc[mi][ni][0], acc[mi][ni][1]);
                *(float2*)(outp + (size_t)r1 * DD + col) =
                    make_float2(acc[mi][ni][2], acc[mi][ni][3]);
            }
        }
    }
}

// ---------------------------------------------------------------------------
// Flash attention: 256 thr (8 warps), 128 queries per CTA, 64-key tiles,
// cp.async double-buffered K/V, ldmatrix feeds, hi/lo 3-pass, warp-level
// triangular skip of fully-masked tiles.
// smem: Q hi/lo 2x18432 + 2 buf x (K/V hi/lo 4x9216) = 110592B.
// ---------------------------------------------------------------------------
#define FBUF 36864
#define FQ   36864

__global__ __launch_bounds__(256)
void flash_tc()
{
    extern __shared__ char fsm[];
    const uint32_t base = smem_u32(fsm);
    const uint32_t uQh = base, uQl = base + 18432u;

    const int tid  = threadIdx.x;
    const int warp = tid >> 5;
    const int lane = tid & 31;
    const int g    = lane >> 2;
    const int t    = lane & 3;
    const int b    = blockIdx.z;
    const int h    = blockIdx.y;
    const int qb   = (gridDim.x - 1) - blockIdx.x;   // heavy blocks first

    const size_t headOff = (size_t)(b * HH + h) * SS * DKK;

    const uint32_t laneA = (uint32_t)(((lane & 7) + ((lane >> 3) & 1) * 8) * SA
                                      + (lane >> 4) * 16);
    const uint32_t laneB = (uint32_t)(((lane & 7) + ((lane >> 4) & 1) * 8) * SA
                                      + ((lane >> 3) & 1) * 16);

    auto load_kv = [&](int kt_tile, int p) {
        uint32_t sb = base + FQ + p * FBUF;
        #pragma unroll
        for (int it = 0; it < 2; ++it) {
            int idx = tid + it * 256;        // 0..511
            int r   = idx >> 3;              // 0..63
            int sg  = idx & 7;
            size_t  s = headOff + (size_t)(kt_tile * 64 + r) * DKK + sg * 8;
            uint32_t d = (uint32_t)(r * SA + sg * 16);
            cp16(sb +          d, g_khi + s);
            cp16(sb + 9216u  + d, g_klo + s);
            cp16(sb + 18432u + d, g_vhi + s);
            cp16(sb + 27648u + d, g_vlo + s);
        }
    };

    // stage Q hi/lo: 128 rows
    #pragma unroll
    for (int it = 0; it < 4; ++it) {
        int idx = tid + it * 256;        // 0..1023
        int r   = idx >> 3;              // 0..127
        int sg  = idx & 7;
        size_t  s = headOff + (size_t)(qb * 128 + r) * DKK + sg * 8;
        uint32_t d = (uint32_t)(r * SA + sg * 16);
        cp16(uQh + d, g_qhi + s);
        cp16(uQl + d, g_qlo + s);
    }
    load_kv(0, 0);
    cpcommit();

    float accO[8][4];
    #pragma unroll
    for (int d = 0; d < 8; ++d)
        #pragma unroll
        for (int r = 0; r < 4; ++r) accO[d][r] = 0.f;
    float m0 = -1e30f, m1 = -1e30f, l0 = 0.f, l1 = 0.f;

    const int qg0  = qb * 128 + warp * 16 + g;   // global q row (and +8)
    const int ntl  = 2 * (qb + 1);

    for (int ch = 0; ch < ntl; ++ch) {
        if (ch < ntl - 1) { load_kv(ch + 1, (ch + 1) & 1); cpcommit(); cpwait<1>(); }
        else              { cpwait<0>(); }
        __syncthreads();

        // warp-level triangular skip: tile fully in the future for this warp?
        const bool active = (ch * 64) <= (qb * 128 + warp * 16 + 15);
        if (active) {
            const uint32_t uKh = base + FQ + (ch & 1) * FBUF;
            const uint32_t uKl = uKh + 9216u;
            const uint32_t uVh = uKh + 18432u;
            const uint32_t uVl = uKh + 27648u;

            // ---- S = Q K^T ----
            float sacc[8][4];
            #pragma unroll
            for (int nt = 0; nt < 8; ++nt)
                #pragma unroll
                for (int r = 0; r < 4; ++r) sacc[nt][r] = 0.f;

            #pragma unroll
            for (int kt = 0; kt < 4; ++kt) {
                const uint32_t ko = (uint32_t)kt * 32u;
                uint32_t qh[4], ql[4];
                uint32_t ao = (uint32_t)(warp * 16 * SA) + ko;
                ldmat4(qh, uQh + ao + laneA);
                ldmat4(ql, uQl + ao + laneA);
                uint32_t kh[4][4], kl[4][4];
                #pragma unroll
                for (int np = 0; np < 4; ++np) {
                    uint32_t bo = (uint32_t)(np * 16 * SA) + ko;
                    ldmat4(kh[np], uKh + bo + laneB);
                    ldmat4(kl[np], uKl + bo + laneB);
                }
                #pragma unroll
                for (int nt = 0; nt < 8; ++nt) {
                    uint32_t b0h = kh[nt >> 1][(nt & 1) * 2];
                    uint32_t b1h = kh[nt >> 1][(nt & 1) * 2 + 1];
                    uint32_t b0l = kl[nt >> 1][(nt & 1) * 2];
                    uint32_t b1l = kl[nt >> 1][(nt & 1) * 2 + 1];
                    mma16816(sacc[nt], qh, b0h, b1h);
                    mma16816(sacc[nt], ql, b0h, b1h);
                    mma16816(sacc[nt], qh, b0l, b1l);
                }
            }

            // ---- causal mask (global indices, last two tiles only) ----
            if (ch >= ntl - 2) {
                #pragma unroll
                for (int nt = 0; nt < 8; ++nt) {
                    int kc = ch * 64 + nt * 8 + 2 * t;
                    if (kc     > qg0)     sacc[nt][0] = -1e30f;
                    if (kc + 1 > qg0)     sacc[nt][1] = -1e30f;
                    if (kc     > qg0 + 8) sacc[nt][2] = -1e30f;
                    if (kc + 1 > qg0 + 8) sacc[nt][3] = -1e30f;
                }
            }

            // ---- online softmax ----
            float mx0 = -1e30f, mx1 = -1e30f;
            #pragma unroll
            for (int nt = 0; nt < 8; ++nt) {
                mx0 = fmaxf(mx0, fmaxf(sacc[nt][0], sacc[nt][1]));
                mx1 = fmaxf(mx1, fmaxf(sacc[nt][2], sacc[nt][3]));
            }
            mx0 = fmaxf(mx0, __shfl_xor_sync(0xffffffff, mx0, 1));
            mx0 = fmaxf(mx0, __shfl_xor_sync(0xffffffff, mx0, 2));
            mx1 = fmaxf(mx1, __shfl_xor_sync(0xffffffff, mx1, 1));
            mx1 = fmaxf(mx1, __shfl_xor_sync(0xffffffff, mx1, 2));
            float mn0 = fmaxf(m0, mx0), mn1 = fmaxf(m1, mx1);
            float cr0 = __expf(m0 - mn0), cr1 = __expf(m1 - mn1);
            m0 = mn0; m1 = mn1;
            l0 *= cr0; l1 *= cr1;
            #pragma unroll
            for (int d = 0; d < 8; ++d) {
                accO[d][0] *= cr0; accO[d][1] *= cr0;
                accO[d][2] *= cr1; accO[d][3] *= cr1;
            }

            // ---- P = exp(S-m) as bf16 hi/lo A-fragments ----
            uint32_t pah[4][4], pal[4][4];
            #pragma unroll
            for (int nt = 0; nt < 8; ++nt) {
                float p0 = __expf(sacc[nt][0] - mn0);
                float p1 = __expf(sacc[nt][1] - mn0);
                float p2 = __expf(sacc[nt][2] - mn1);
                float p3 = __expf(sacc[nt][3] - mn1);
                l0 += p0 + p1;
                l1 += p2 + p3;
                uint32_t h01, l01, h23, l23;
                split2(p0, p1, h01, l01);
                split2(p2, p3, h23, l23);
                int kt = nt >> 1;
                if ((nt & 1) == 0) {
                    pah[kt][0] = h01; pah[kt][1] = h23;
                    pal[kt][0] = l01; pal[kt][1] = l23;
                } else {
                    pah[kt][2] = h01; pah[kt][3] = h23;
                    pal[kt][2] = l01; pal[kt][3] = l23;
                }
            }

            // ---- O += P V ----
            const int mat = lane >> 3;
            const int rr  = lane & 7;
            #pragma unroll
            for (int kt = 0; kt < 4; ++kt) {
                #pragma unroll
                for (int pr = 0; pr < 4; ++pr) {
                    uint32_t off = (uint32_t)((kt * 16 + rr + (mat & 1) * 8) * SA)
                                 + (uint32_t)((pr * 16 + (mat >> 1) * 8) * 2);
                    uint32_t vh[4], vl[4];
                    ldmat4t(vh, uVh + off);
                    mma16816(accO[2 * pr],     pah[kt], vh[0], vh[1]);
                    mma16816(accO[2 * pr],     pal[kt], vh[0], vh[1]);
                    mma16816(accO[2 * pr + 1], pah[kt], vh[2], vh[3]);
                    mma16816(accO[2 * pr + 1], pal[kt], vh[2], vh[3]);
                    ldmat4t(vl, uVl + off);
                    mma16816(accO[2 * pr],     pah[kt], vl[0], vl[1]);
                    mma16816(accO[2 * pr + 1], pah[kt], vl[2], vl[3]);
                }
            }
        }
        __syncthreads();
    }

    // ---- finalize: write ctx as bf16 hi/lo ----
    l0 += __shfl_xor_sync(0xffffffff, l0, 1);
    l0 += __shfl_xor_sync(0xffffffff, l0, 2);
    l1 += __shfl_xor_sync(0xffffffff, l1, 1);
    l1 += __shfl_xor_sync(0xffffffff, l1, 2);
    float inv0 = 1.0f / l0, inv1 = 1.0f / l1;

    size_t base0 = ((size_t)b * SS + qg0) * DD + h * DKK;
    size_t base1 = base0 + (size_t)8 * DD;
    #pragma unroll
    for (int d = 0; d < 8; ++d) {
        int col = d * 8 + 2 * t;
        uint32_t hi, lo;
        split2(accO[d][0] * inv0, accO[d][1] * inv0, hi, lo);
        *(uint32_t*)(g_chi + base0 + col) = hi;
        *(uint32_t*)(g_clo + base0 + col) = lo;
        split2(accO[d][2] * inv1, accO[d][3] * inv1, hi, lo);
        *(uint32_t*)(g_chi + base1 + col) = hi;
        *(uint32_t*)(g_clo + base1 + col) = lo;
    }
}

// ---------------------------------------------------------------------------
extern "C" void kernel_launch(void* const* d_in, const int* in_sizes, int n_in,
                              void* d_out, int out_size)
{
    (void)in_sizes; (void)n_in; (void)out_size;
    const float* Q  = (const float*)d_in[0];
    const float* K  = (const float*)d_in[1];
    const float* V  = (const float*)d_in[2];
    const float* Wq = (const float*)d_in[4];
    const float* Wk = (const float*)d_in[5];
    const float* Wv = (const float*)d_in[6];
    const float* Wo = (const float*)d_in[7];
    float* out = (float*)d_out;

    constexpr int GEMM_SMEM  = 2 * GBUF;      // 147456
    constexpr int FLASH_SMEM = FQ + 2 * FBUF; // 110592
    static bool attr_done = false;
    if (!attr_done) {
        cudaFuncSetAttribute(gemm_bf<0>,
                             cudaFuncAttributeMaxDynamicSharedMemorySize, GEMM_SMEM);
        cudaFuncSetAttribute(gemm_bf<1>,
                             cudaFuncAttributeMaxDynamicSharedMemorySize, GEMM_SMEM);
        cudaFuncSetAttribute(flash_tc,
                             cudaFuncAttributeMaxDynamicSharedMemorySize, FLASH_SMEM);
        attr_done = true;
    }

    conv_x<<<dim3(XN / 4 / 256, 1, 3), 256>>>(Q, K, V);
    conv_w<<<dim3(WN / 4 / 256, 1, 4), 256>>>(Wq, Wk, Wv, Wo);

    gemm_bf<0><<<dim3(DD / 128, (BB * SS) / 128, 3), 256, GEMM_SMEM>>>(nullptr);

    flash_tc<<<dim3(SS / 128, HH, BB), 256, FLASH_SMEM>>>();

    gemm_bf<1><<<dim3(DD / 128, (BB * SS) / 128, 1), 256, GEMM_SMEM>>>(out);
}

// round 8
// speedup vs baseline: 1.2055x; 1.2055x over previous
#include <cuda_runtime.h>
#include <cuda_bf16.h>
#include <cuda_fp16.h>
#include <math.h>
#include <stdint.h>

#define BB   2
#define SS   2048
#define DD   768
#define HH   12
#define DKK  64

#define XN 3145728   // 4096*768
#define WN 589824    // 768*768
#define HN 3145728   // BB*HH*SS*DKK
#define CN 3145728   // BB*SS*DD

// scratch (allocation-free)
__device__ __align__(128) __nv_bfloat16 g_xhi[3 * XN];
__device__ __align__(128) __nv_bfloat16 g_xlo[3 * XN];
__device__ __align__(128) __nv_bfloat16 g_whi[4 * WN];
__device__ __align__(128) __nv_bfloat16 g_wlo[4 * WN];
__device__ __align__(128) __half        g_qh[HN];
__device__ __align__(128) __half        g_ql[HN];
__device__ __align__(128) __half        g_kh[HN];
__device__ __align__(128) __half        g_kl[HN];
__device__ __align__(128) __half        g_vh[HN];
__device__ __align__(128) __nv_bfloat16 g_chi[CN];
__device__ __align__(128) __nv_bfloat16 g_clo[CN];

// ------------------------------ helpers -------------------------------------
__device__ __forceinline__ uint32_t smem_u32(const void* p) {
    return (uint32_t)__cvta_generic_to_shared(p);
}
__device__ __forceinline__ void mma16816(float* c, const uint32_t* a,
                                         uint32_t b0, uint32_t b1) {
    asm volatile(
        "mma.sync.aligned.m16n8k16.row.col.f32.bf16.bf16.f32 "
        "{%0,%1,%2,%3}, {%4,%5,%6,%7}, {%8,%9}, {%0,%1,%2,%3};"
        : "+f"(c[0]), "+f"(c[1]), "+f"(c[2]), "+f"(c[3])
        : "r"(a[0]), "r"(a[1]), "r"(a[2]), "r"(a[3]), "r"(b0), "r"(b1));
}
__device__ __forceinline__ void mma16816h(float* c, const uint32_t* a,
                                          uint32_t b0, uint32_t b1) {
    asm volatile(
        "mma.sync.aligned.m16n8k16.row.col.f32.f16.f16.f32 "
        "{%0,%1,%2,%3}, {%4,%5,%6,%7}, {%8,%9}, {%0,%1,%2,%3};"
        : "+f"(c[0]), "+f"(c[1]), "+f"(c[2]), "+f"(c[3])
        : "r"(a[0]), "r"(a[1]), "r"(a[2]), "r"(a[3]), "r"(b0), "r"(b1));
}
__device__ __forceinline__ void ldmat4(uint32_t* r, uint32_t addr) {
    asm volatile(
        "ldmatrix.sync.aligned.m8n8.x4.shared.b16 {%0,%1,%2,%3}, [%4];"
        : "=r"(r[0]), "=r"(r[1]), "=r"(r[2]), "=r"(r[3]) : "r"(addr));
}
__device__ __forceinline__ void ldmat4t(uint32_t* r, uint32_t addr) {
    asm volatile(
        "ldmatrix.sync.aligned.m8n8.x4.trans.shared.b16 {%0,%1,%2,%3}, [%4];"
        : "=r"(r[0]), "=r"(r[1]), "=r"(r[2]), "=r"(r[3]) : "r"(addr));
}
__device__ __forceinline__ uint32_t pkbf(float a, float b) {
    __nv_bfloat162 h = __floats2bfloat162_rn(a, b);
    return *(uint32_t*)&h;
}
__device__ __forceinline__ void split2(float x, float y, uint32_t &hi, uint32_t &lo) {
    float hx = __bfloat162float(__float2bfloat16(x));
    float hy = __bfloat162float(__float2bfloat16(y));
    hi = pkbf(x, y);
    lo = pkbf(x - hx, y - hy);
}
__device__ __forceinline__ uint32_t pkhf(float a, float b) {
    __half2 h = __floats2half2_rn(a, b);
    return *(uint32_t*)&h;
}
__device__ __forceinline__ void split2h(float x, float y, uint32_t &hi, uint32_t &lo) {
    float hx = __half2float(__float2half_rn(x));
    float hy = __half2float(__float2half_rn(y));
    hi = pkhf(x, y);
    lo = pkhf(x - hx, y - hy);
}
__device__ __forceinline__ float ex2f(float x) {
    float r; asm("ex2.approx.ftz.f32 %0, %1;" : "=f"(r) : "f"(x)); return r;
}
__device__ __forceinline__ void cp16(uint32_t dst, const void* src) {
    asm volatile("cp.async.cg.shared.global [%0], [%1], 16;"
                 :: "r"(dst), "l"(src));
}
__device__ __forceinline__ void cpcommit() {
    asm volatile("cp.async.commit_group;" ::: "memory");
}
template<int N>
__device__ __forceinline__ void cpwait() {
    asm volatile("cp.async.wait_group %0;" :: "n"(N) : "memory");
}

#define SA 144
#define QSCALE 0.18033688f   // 0.125 * log2(e): scores in base-2 units

// ---------------------------------------------------------------------------
// Convert kernels (GEMM operands stay bf16 hi/lo)
// ---------------------------------------------------------------------------
__global__ __launch_bounds__(256)
void conv_x(const float* __restrict__ x0, const float* __restrict__ x1,
            const float* __restrict__ x2)
{
    const float* src = (blockIdx.z == 0) ? x0 : (blockIdx.z == 1) ? x1 : x2;
    size_t off = (size_t)blockIdx.z * XN;
    size_t i4  = ((size_t)blockIdx.x * 256 + threadIdx.x) * 4;
    float4 v = *(const float4*)(src + i4);
    uint32_t h0, l0, h1, l1;
    split2(v.x, v.y, h0, l0);
    split2(v.z, v.w, h1, l1);
    *(uint2*)(g_xhi + off + i4) = make_uint2(h0, h1);
    *(uint2*)(g_xlo + off + i4) = make_uint2(l0, l1);
}

__global__ __launch_bounds__(256)
void conv_w(const float* __restrict__ w0, const float* __restrict__ w1,
            const float* __restrict__ w2, const float* __restrict__ w3)
{
    const float* src = (blockIdx.z == 0) ? w0 : (blockIdx.z == 1) ? w1
                     : (blockIdx.z == 2) ? w2 : w3;
    size_t off = (size_t)blockIdx.z * WN;
    size_t i4  = ((size_t)blockIdx.x * 256 + threadIdx.x) * 4;
    float4 v = *(const float4*)(src + i4);
    uint32_t h0, l0, h1, l1;
    split2(v.x, v.y, h0, l0);
    split2(v.z, v.w, h1, l1);
    *(uint2*)(g_whi + off + i4) = make_uint2(h0, h1);
    *(uint2*)(g_wlo + off + i4) = make_uint2(l0, l1);
}

// ---------------------------------------------------------------------------
// Pipelined HMMA GEMM (bf16 3-pass).  MODE 0 epilogue -> fp16 q/k/v scratch.
// ---------------------------------------------------------------------------
#define GBUF 73728

template<int MODE>
__global__ __launch_bounds__(256)
void gemm_bf(float* __restrict__ outp)
{
    extern __shared__ char sm[];
    const uint32_t base = smem_u32(sm);

    const int tid  = threadIdx.x;
    const int warp = tid >> 5;
    const int lane = tid & 31;
    const int g    = lane >> 2;
    const int t    = lane & 3;
    const int wm   = (warp >> 2) * 64;
    const int wn   = (warp & 3) * 32;
    const int rowBase = blockIdx.y * 128;
    const int colBase = blockIdx.x * 128;
    const int z = blockIdx.z;

    const __nv_bfloat16 *Ahi, *Alo, *Bhi, *Blo;
    if (MODE == 0) {
        Ahi = g_xhi + (size_t)z * XN; Alo = g_xlo + (size_t)z * XN;
        Bhi = g_whi + (size_t)z * WN; Blo = g_wlo + (size_t)z * WN;
    } else {
        Ahi = g_chi; Alo = g_clo;
        Bhi = g_whi + (size_t)3 * WN; Blo = g_wlo + (size_t)3 * WN;
    }

    const uint32_t laneA = (uint32_t)(((lane & 7) + ((lane >> 3) & 1) * 8) * SA
                                      + (lane >> 4) * 16);
    const uint32_t laneB = (uint32_t)(((lane & 7) + ((lane >> 4) & 1) * 8) * SA
                                      + ((lane >> 3) & 1) * 16);

    float acc[4][4][4];
    #pragma unroll
    for (int mi = 0; mi < 4; ++mi)
        #pragma unroll
        for (int ni = 0; ni < 4; ++ni)
            #pragma unroll
            for (int r = 0; r < 4; ++r) acc[mi][ni][r] = 0.f;

    auto load_chunk = [&](int ch, int p) {
        const int k0 = ch * 64;
        uint32_t sb = base + p * GBUF;
        #pragma unroll
        for (int it = 0; it < 4; ++it) {
            int idx = tid + it * 256;
            int r   = idx >> 3;
            int sg  = idx & 7;
            uint32_t d = (uint32_t)(r * SA + sg * 16);
            cp16(sb +          d, Ahi + (size_t)(rowBase + r) * DD + k0 + sg * 8);
            cp16(sb + 18432u + d, Alo + (size_t)(rowBase + r) * DD + k0 + sg * 8);
            cp16(sb + 36864u + d, Bhi + (size_t)(colBase + r) * DD + k0 + sg * 8);
            cp16(sb + 55296u + d, Blo + (size_t)(colBase + r) * DD + k0 + sg * 8);
        }
    };

    load_chunk(0, 0);
    cpcommit();

    for (int ch = 0; ch < 12; ++ch) {
        if (ch < 11) { load_chunk(ch + 1, (ch + 1) & 1); cpcommit(); cpwait<1>(); }
        else         { cpwait<0>(); }
        __syncthreads();

        const uint32_t uAh = base + (ch & 1) * GBUF;
        const uint32_t uAl = uAh + 18432u;
        const uint32_t uBh = uAh + 36864u;
        const uint32_t uBl = uAh + 55296u;

        #pragma unroll
        for (int kt = 0; kt < 4; ++kt) {
            const uint32_t ko = (uint32_t)kt * 32u;
            uint32_t afh[4][4], afl[4][4];
            #pragma unroll
            for (int mi = 0; mi < 4; ++mi) {
                uint32_t ao = (uint32_t)((wm + mi * 16) * SA) + ko;
                ldmat4(afh[mi], uAh + ao + laneA);
                ldmat4(afl[mi], uAl + ao + laneA);
            }
            uint32_t bh[2][4], bl[2][4];
            #pragma unroll
            for (int np = 0; np < 2; ++np) {
                uint32_t bo = (uint32_t)((wn + np * 16) * SA) + ko;
                ldmat4(bh[np], uBh + bo + laneB);
                ldmat4(bl[np], uBl + bo + laneB);
            }
            #pragma unroll
            for (int ni = 0; ni < 4; ++ni) {
                uint32_t b0h = bh[ni >> 1][(ni & 1) * 2];
                uint32_t b1h = bh[ni >> 1][(ni & 1) * 2 + 1];
                uint32_t b0l = bl[ni >> 1][(ni & 1) * 2];
                uint32_t b1l = bl[ni >> 1][(ni & 1) * 2 + 1];
                #pragma unroll
                for (int mi = 0; mi < 4; ++mi) {
                    mma16816(acc[mi][ni], afh[mi], b0h, b1h);
                    mma16816(acc[mi][ni], afl[mi], b0h, b1h);
                    mma16816(acc[mi][ni], afh[mi], b0l, b1l);
                }
            }
        }
        __syncthreads();
    }

    #pragma unroll
    for (int mi = 0; mi < 4; ++mi) {
        int r0 = rowBase + wm + mi * 16 + g;
        int r1 = r0 + 8;
        #pragma unroll
        for (int ni = 0; ni < 4; ++ni) {
            int col = colBase + wn + ni * 8 + 2 * t;
            if (MODE == 0) {
                int h = col >> 6, dk = col & 63;
                int b0 = r0 >> 11, s0 = r0 & (SS - 1);
                int b1 = r1 >> 11, s1 = r1 & (SS - 1);
                size_t i0 = (((size_t)b0 * HH + h) * SS + s0) * DKK + dk;
                size_t i1 = (((size_t)b1 * HH + h) * SS + s1) * DKK + dk;
                if (z == 2) {          // V: single fp16
                    *(uint32_t*)(g_vh + i0) = pkhf(acc[mi][ni][0], acc[mi][ni][1]);
                    *(uint32_t*)(g_vh + i1) = pkhf(acc[mi][ni][2], acc[mi][ni][3]);
                } else {               // Q (scaled to base-2 units) / K: fp16 hi/lo
                    const float sc = (z == 0) ? QSCALE : 1.0f;
                    __half* dhi = (z == 0) ? g_qh : g_kh;
                    __half* dlo = (z == 0) ? g_ql : g_kl;
                    uint32_t hi, lo;
                    split2h(acc[mi][ni][0] * sc, acc[mi][ni][1] * sc, hi, lo);
                    *(uint32_t*)(dhi + i0) = hi;
                    *(uint32_t*)(dlo + i0) = lo;
                    split2h(acc[mi][ni][2] * sc, acc[mi][ni][3] * sc, hi, lo);
                    *(uint32_t*)(dhi + i1) = hi;
                    *(uint32_t*)(dlo + i1) = lo;
                }
            } else {
                *(float2*)(outp + (size_t)r0 * DD + col) =
                    make_float2(acc[mi][ni][0], acc[mi][ni][1]);
                *(float2*)(outp + (size_t)r1 * DD + col) =
                    make_float2(acc[mi][ni][2], acc[mi][ni][3]);
            }
        }
    }
}

// ---------------------------------------------------------------------------
// Flash attention (fp16 path): 128 thr (4 warps), 64 q/CTA, 64-key tiles.
// S = QK^T fp16 hi/lo 3-pass; softmax in base-2 (ex2); P single fp16;
// O += P V single pass (V fp16).  cp.async double-buffered K/V.
// smem: Q hi/lo 2x9216 + 2 buf x (Kh,Kl,V x 9216) = 73728B -> 3 CTAs/SM.
// ---------------------------------------------------------------------------
#define FBUF 27648
#define FQ   18432

__global__ __launch_bounds__(128)
void flash_tc()
{
    extern __shared__ char fsm[];
    const uint32_t base = smem_u32(fsm);
    const uint32_t uQh = base, uQl = base + 9216u;

    const int tid  = threadIdx.x;
    const int warp = tid >> 5;
    const int lane = tid & 31;
    const int g    = lane >> 2;
    const int t    = lane & 3;
    const int b    = blockIdx.z;
    const int h    = blockIdx.y;
    const int qb   = (gridDim.x - 1) - blockIdx.x;   // heavy blocks first

    const size_t headOff = (size_t)(b * HH + h) * SS * DKK;

    const uint32_t laneA = (uint32_t)(((lane & 7) + ((lane >> 3) & 1) * 8) * SA
                                      + (lane >> 4) * 16);
    const uint32_t laneB = (uint32_t)(((lane & 7) + ((lane >> 4) & 1) * 8) * SA
                                      + ((lane >> 3) & 1) * 16);

    auto load_kv = [&](int kt_tile, int p) {
        uint32_t sb = base + FQ + p * FBUF;
        #pragma unroll
        for (int it = 0; it < 4; ++it) {
            int idx = tid + it * 128;        // 0..511
            int r   = idx >> 3;              // 0..63
            int sg  = idx & 7;
            size_t  s = headOff + (size_t)(kt_tile * 64 + r) * DKK + sg * 8;
            uint32_t d = (uint32_t)(r * SA + sg * 16);
            cp16(sb +          d, g_kh + s);
            cp16(sb + 9216u  + d, g_kl + s);
            cp16(sb + 18432u + d, g_vh + s);
        }
    };

    // stage Q hi/lo
    #pragma unroll
    for (int it = 0; it < 4; ++it) {
        int idx = tid + it * 128;
        int r   = idx >> 3;
        int sg  = idx & 7;
        size_t  s = headOff + (size_t)(qb * 64 + r) * DKK + sg * 8;
        uint32_t d = (uint32_t)(r * SA + sg * 16);
        cp16(uQh + d, g_qh + s);
        cp16(uQl + d, g_ql + s);
    }
    load_kv(0, 0);
    cpcommit();

    float accO[8][4];
    #pragma unroll
    for (int d = 0; d < 8; ++d)
        #pragma unroll
        for (int r = 0; r < 4; ++r) accO[d][r] = 0.f;
    float m0 = -1e30f, m1 = -1e30f, l0 = 0.f, l1 = 0.f;

    const int qrow = warp * 16 + g;
    const int ntl  = qb + 1;

    for (int ch = 0; ch < ntl; ++ch) {
        if (ch < ntl - 1) { load_kv(ch + 1, (ch + 1) & 1); cpcommit(); cpwait<1>(); }
        else              { cpwait<0>(); }
        __syncthreads();

        const uint32_t uKh = base + FQ + (ch & 1) * FBUF;
        const uint32_t uKl = uKh + 9216u;
        const uint32_t uV  = uKh + 18432u;

        // ---- S = Q K^T (fp16 3-pass) ----
        float sacc[8][4];
        #pragma unroll
        for (int nt = 0; nt < 8; ++nt)
            #pragma unroll
            for (int r = 0; r < 4; ++r) sacc[nt][r] = 0.f;

        #pragma unroll
        for (int kt = 0; kt < 4; ++kt) {
            const uint32_t ko = (uint32_t)kt * 32u;
            uint32_t qh[4], ql[4];
            uint32_t ao = (uint32_t)(warp * 16 * SA) + ko;
            ldmat4(qh, uQh + ao + laneA);
            ldmat4(ql, uQl + ao + laneA);
            uint32_t kh[4][4], kl[4][4];
            #pragma unroll
            for (int np = 0; np < 4; ++np) {
                uint32_t bo = (uint32_t)(np * 16 * SA) + ko;
                ldmat4(kh[np], uKh + bo + laneB);
                ldmat4(kl[np], uKl + bo + laneB);
            }
            #pragma unroll
            for (int nt = 0; nt < 8; ++nt) {
                uint32_t b0h = kh[nt >> 1][(nt & 1) * 2];
                uint32_t b1h = kh[nt >> 1][(nt & 1) * 2 + 1];
                uint32_t b0l = kl[nt >> 1][(nt & 1) * 2];
                uint32_t b1l = kl[nt >> 1][(nt & 1) * 2 + 1];
                mma16816h(sacc[nt], qh, b0h, b1h);
                mma16816h(sacc[nt], ql, b0h, b1h);
                mma16816h(sacc[nt], qh, b0l, b1l);
            }
        }

        // ---- causal mask on diagonal tile ----
        if (ch == qb) {
            #pragma unroll
            for (int nt = 0; nt < 8; ++nt) {
                int kc = nt * 8 + 2 * t;
                if (kc     > qrow)     sacc[nt][0] = -1e30f;
                if (kc + 1 > qrow)     sacc[nt][1] = -1e30f;
                if (kc     > qrow + 8) sacc[nt][2] = -1e30f;
                if (kc + 1 > qrow + 8) sacc[nt][3] = -1e30f;
            }
        }

        // ---- online softmax (base-2) ----
        float mx0 = -1e30f, mx1 = -1e30f;
        #pragma unroll
        for (int nt = 0; nt < 8; ++nt) {
            mx0 = fmaxf(mx0, fmaxf(sacc[nt][0], sacc[nt][1]));
            mx1 = fmaxf(mx1, fmaxf(sacc[nt][2], sacc[nt][3]));
        }
        mx0 = fmaxf(mx0, __shfl_xor_sync(0xffffffff, mx0, 1));
        mx0 = fmaxf(mx0, __shfl_xor_sync(0xffffffff, mx0, 2));
        mx1 = fmaxf(mx1, __shfl_xor_sync(0xffffffff, mx1, 1));
        mx1 = fmaxf(mx1, __shfl_xor_sync(0xffffffff, mx1, 2));
        float mn0 = fmaxf(m0, mx0), mn1 = fmaxf(m1, mx1);
        float cr0 = ex2f(m0 - mn0), cr1 = ex2f(m1 - mn1);
        m0 = mn0; m1 = mn1;
        l0 *= cr0; l1 *= cr1;
        #pragma unroll
        for (int d = 0; d < 8; ++d) {
            accO[d][0] *= cr0; accO[d][1] *= cr0;
            accO[d][2] *= cr1; accO[d][3] *= cr1;
        }

        // ---- P = 2^(S-m), single fp16 A-fragments ----
        uint32_t pah[4][4];
        #pragma unroll
        for (int nt = 0; nt < 8; ++nt) {
            float p0 = ex2f(sacc[nt][0] - mn0);
            float p1 = ex2f(sacc[nt][1] - mn0);
            float p2 = ex2f(sacc[nt][2] - mn1);
            float p3 = ex2f(sacc[nt][3] - mn1);
            l0 += p0 + p1;
            l1 += p2 + p3;
            int kt = nt >> 1;
            if ((nt & 1) == 0) {
                pah[kt][0] = pkhf(p0, p1);
                pah[kt][1] = pkhf(p2, p3);
            } else {
                pah[kt][2] = pkhf(p0, p1);
                pah[kt][3] = pkhf(p2, p3);
            }
        }

        // ---- O += P V (single pass) ----
        const int mat = lane >> 3;
        const int rr  = lane & 7;
        #pragma unroll
        for (int kt = 0; kt < 4; ++kt) {
            #pragma unroll
            for (int pr = 0; pr < 4; ++pr) {
                uint32_t off = (uint32_t)((kt * 16 + rr + (mat & 1) * 8) * SA)
                             + (uint32_t)((pr * 16 + (mat >> 1) * 8) * 2);
                uint32_t vv[4];
                ldmat4t(vv, uV + off);
                mma16816h(accO[2 * pr],     pah[kt], vv[0], vv[1]);
                mma16816h(accO[2 * pr + 1], pah[kt], vv[2], vv[3]);
            }
        }
        __syncthreads();
    }

    // ---- finalize: write ctx as bf16 hi/lo ----
    l0 += __shfl_xor_sync(0xffffffff, l0, 1);
    l0 += __shfl_xor_sync(0xffffffff, l0, 2);
    l1 += __shfl_xor_sync(0xffffffff, l1, 1);
    l1 += __shfl_xor_sync(0xffffffff, l1, 2);
    float inv0 = 1.0f / l0, inv1 = 1.0f / l1;

    int q0 = qb * 64 + qrow;
    size_t base0 = ((size_t)b * SS + q0) * DD + h * DKK;
    size_t base1 = base0 + (size_t)8 * DD;
    #pragma unroll
    for (int d = 0; d < 8; ++d) {
        int col = d * 8 + 2 * t;
        uint32_t hi, lo;
        split2(accO[d][0] * inv0, accO[d][1] * inv0, hi, lo);
        *(uint32_t*)(g_chi + base0 + col) = hi;
        *(uint32_t*)(g_clo + base0 + col) = lo;
        split2(accO[d][2] * inv1, accO[d][3] * inv1, hi, lo);
        *(uint32_t*)(g_chi + base1 + col) = hi;
        *(uint32_t*)(g_clo + base1 + col) = lo;
    }
}

// ---------------------------------------------------------------------------
extern "C" void kernel_launch(void* const* d_in, const int* in_sizes, int n_in,
                              void* d_out, int out_size)
{
    (void)in_sizes; (void)n_in; (void)out_size;
    const float* Q  = (const float*)d_in[0];
    const float* K  = (const float*)d_in[1];
    const float* V  = (const float*)d_in[2];
    const float* Wq = (const float*)d_in[4];
    const float* Wk = (const float*)d_in[5];
    const float* Wv = (const float*)d_in[6];
    const float* Wo = (const float*)d_in[7];
    float* out = (float*)d_out;

    constexpr int GEMM_SMEM  = 2 * GBUF;      // 147456
    constexpr int FLASH_SMEM = FQ + 2 * FBUF; // 73728
    static bool attr_done = false;
    if (!attr_done) {
        cudaFuncSetAttribute(gemm_bf<0>,
                             cudaFuncAttributeMaxDynamicSharedMemorySize, GEMM_SMEM);
        cudaFuncSetAttribute(gemm_bf<1>,
                             cudaFuncAttributeMaxDynamicSharedMemorySize, GEMM_SMEM);
        cudaFuncSetAttribute(flash_tc,
                             cudaFuncAttributeMaxDynamicSharedMemorySize, FLASH_SMEM);
        attr_done = true;
    }

    conv_x<<<dim3(XN / 4 / 256, 1, 3), 256>>>(Q, K, V);
    conv_w<<<dim3(WN / 4 / 256, 1, 4), 256>>>(Wq, Wk, Wv, Wo);

    gemm_bf<0><<<dim3(DD / 128, (BB * SS) / 128, 3), 256, GEMM_SMEM>>>(nullptr);

    flash_tc<<<dim3(SS / 64, HH, BB), 128, FLASH_SMEM>>>();

    gemm_bf<1><<<dim3(DD / 128, (BB * SS) / 128, 1), 256, GEMM_SMEM>>>(out);
}

// round 9
// speedup vs baseline: 1.3910x; 1.1539x over previous
#include <cuda_runtime.h>
#include <cuda_bf16.h>
#include <cuda_fp16.h>
#include <math.h>
#include <stdint.h>

#define BB   2
#define SS   2048
#define DD   768
#define HH   12
#define DKK  64

#define XN 3145728   // 4096*768
#define WN 589824    // 768*768
#define HN 3145728   // BB*HH*SS*DKK
#define CN 3145728   // BB*SS*DD

// scratch (allocation-free)
__device__ __align__(128) __nv_bfloat16 g_xhi[3 * XN];
__device__ __align__(128) __nv_bfloat16 g_xlo[3 * XN];
__device__ __align__(128) __nv_bfloat16 g_whi[4 * WN];
__device__ __align__(128) __nv_bfloat16 g_wlo[4 * WN];
__device__ __align__(128) __half        g_qh[HN];   // fp16, pre-scaled by 0.125*log2e
__device__ __align__(128) __half        g_kh[HN];   // fp16
__device__ __align__(128) __half        g_vh[HN];   // fp16
__device__ __align__(128) __nv_bfloat16 g_chi[CN];
__device__ __align__(128) __nv_bfloat16 g_clo[CN];

// ------------------------------ helpers -------------------------------------
__device__ __forceinline__ uint32_t smem_u32(const void* p) {
    return (uint32_t)__cvta_generic_to_shared(p);
}
__device__ __forceinline__ void mma16816(float* c, const uint32_t* a,
                                         uint32_t b0, uint32_t b1) {
    asm volatile(
        "mma.sync.aligned.m16n8k16.row.col.f32.bf16.bf16.f32 "
        "{%0,%1,%2,%3}, {%4,%5,%6,%7}, {%8,%9}, {%0,%1,%2,%3};"
        : "+f"(c[0]), "+f"(c[1]), "+f"(c[2]), "+f"(c[3])
        : "r"(a[0]), "r"(a[1]), "r"(a[2]), "r"(a[3]), "r"(b0), "r"(b1));
}
__device__ __forceinline__ void mma16816h(float* c, const uint32_t* a,
                                          uint32_t b0, uint32_t b1) {
    asm volatile(
        "mma.sync.aligned.m16n8k16.row.col.f32.f16.f16.f32 "
        "{%0,%1,%2,%3}, {%4,%5,%6,%7}, {%8,%9}, {%0,%1,%2,%3};"
        : "+f"(c[0]), "+f"(c[1]), "+f"(c[2]), "+f"(c[3])
        : "r"(a[0]), "r"(a[1]), "r"(a[2]), "r"(a[3]), "r"(b0), "r"(b1));
}
__device__ __forceinline__ void ldmat4(uint32_t* r, uint32_t addr) {
    asm volatile(
        "ldmatrix.sync.aligned.m8n8.x4.shared.b16 {%0,%1,%2,%3}, [%4];"
        : "=r"(r[0]), "=r"(r[1]), "=r"(r[2]), "=r"(r[3]) : "r"(addr));
}
__device__ __forceinline__ void ldmat4t(uint32_t* r, uint32_t addr) {
    asm volatile(
        "ldmatrix.sync.aligned.m8n8.x4.trans.shared.b16 {%0,%1,%2,%3}, [%4];"
        : "=r"(r[0]), "=r"(r[1]), "=r"(r[2]), "=r"(r[3]) : "r"(addr));
}
__device__ __forceinline__ uint32_t pkbf(float a, float b) {
    __nv_bfloat162 h = __floats2bfloat162_rn(a, b);
    return *(uint32_t*)&h;
}
__device__ __forceinline__ void split2(float x, float y, uint32_t &hi, uint32_t &lo) {
    float hx = __bfloat162float(__float2bfloat16(x));
    float hy = __bfloat162float(__float2bfloat16(y));
    hi = pkbf(x, y);
    lo = pkbf(x - hx, y - hy);
}
__device__ __forceinline__ uint32_t pkhf(float a, float b) {
    __half2 h = __floats2half2_rn(a, b);
    return *(uint32_t*)&h;
}
__device__ __forceinline__ float ex2f(float x) {
    float r; asm("ex2.approx.ftz.f32 %0, %1;" : "=f"(r) : "f"(x)); return r;
}
__device__ __forceinline__ void cp16(uint32_t dst, const void* src) {
    asm volatile("cp.async.cg.shared.global [%0], [%1], 16;"
                 :: "r"(dst), "l"(src));
}
__device__ __forceinline__ void cpcommit() {
    asm volatile("cp.async.commit_group;" ::: "memory");
}
template<int N>
__device__ __forceinline__ void cpwait() {
    asm volatile("cp.async.wait_group %0;" :: "n"(N) : "memory");
}

#define SA 144
#define QSCALE 0.18033688f   // 0.125 * log2(e)

// ---------------------------------------------------------------------------
// Convert kernels (GEMM operands bf16 hi/lo)
// ---------------------------------------------------------------------------
__global__ __launch_bounds__(256)
void conv_x(const float* __restrict__ x0, const float* __restrict__ x1,
            const float* __restrict__ x2)
{
    const float* src = (blockIdx.z == 0) ? x0 : (blockIdx.z == 1) ? x1 : x2;
    size_t off = (size_t)blockIdx.z * XN;
    size_t i4  = ((size_t)blockIdx.x * 256 + threadIdx.x) * 4;
    float4 v = *(const float4*)(src + i4);
    uint32_t h0, l0, h1, l1;
    split2(v.x, v.y, h0, l0);
    split2(v.z, v.w, h1, l1);
    *(uint2*)(g_xhi + off + i4) = make_uint2(h0, h1);
    *(uint2*)(g_xlo + off + i4) = make_uint2(l0, l1);
}

__global__ __launch_bounds__(256)
void conv_w(const float* __restrict__ w0, const float* __restrict__ w1,
            const float* __restrict__ w2, const float* __restrict__ w3)
{
    const float* src = (blockIdx.z == 0) ? w0 : (blockIdx.z == 1) ? w1
                     : (blockIdx.z == 2) ? w2 : w3;
    size_t off = (size_t)blockIdx.z * WN;
    size_t i4  = ((size_t)blockIdx.x * 256 + threadIdx.x) * 4;
    float4 v = *(const float4*)(src + i4);
    uint32_t h0, l0, h1, l1;
    split2(v.x, v.y, h0, l0);
    split2(v.z, v.w, h1, l1);
    *(uint2*)(g_whi + off + i4) = make_uint2(h0, h1);
    *(uint2*)(g_wlo + off + i4) = make_uint2(l0, l1);
}

// ---------------------------------------------------------------------------
// Pipelined HMMA GEMM (bf16 3-pass), single __syncthreads per chunk.
// MODE 0 epilogue -> single fp16 q/k/v scratch (q pre-scaled).
// ---------------------------------------------------------------------------
#define GBUF 73728

template<int MODE>
__global__ __launch_bounds__(256)
void gemm_bf(float* __restrict__ outp)
{
    extern __shared__ char sm[];
    const uint32_t base = smem_u32(sm);

    const int tid  = threadIdx.x;
    const int warp = tid >> 5;
    const int lane = tid & 31;
    const int g    = lane >> 2;
    const int t    = lane & 3;
    const int wm   = (warp >> 2) * 64;
    const int wn   = (warp & 3) * 32;
    const int rowBase = blockIdx.y * 128;
    const int colBase = blockIdx.x * 128;
    const int z = blockIdx.z;

    const __nv_bfloat16 *Ahi, *Alo, *Bhi, *Blo;
    if (MODE == 0) {
        Ahi = g_xhi + (size_t)z * XN; Alo = g_xlo + (size_t)z * XN;
        Bhi = g_whi + (size_t)z * WN; Blo = g_wlo + (size_t)z * WN;
    } else {
        Ahi = g_chi; Alo = g_clo;
        Bhi = g_whi + (size_t)3 * WN; Blo = g_wlo + (size_t)3 * WN;
    }

    const uint32_t laneA = (uint32_t)(((lane & 7) + ((lane >> 3) & 1) * 8) * SA
                                      + (lane >> 4) * 16);
    const uint32_t laneB = (uint32_t)(((lane & 7) + ((lane >> 4) & 1) * 8) * SA
                                      + ((lane >> 3) & 1) * 16);

    float acc[4][4][4];
    #pragma unroll
    for (int mi = 0; mi < 4; ++mi)
        #pragma unroll
        for (int ni = 0; ni < 4; ++ni)
            #pragma unroll
            for (int r = 0; r < 4; ++r) acc[mi][ni][r] = 0.f;

    auto load_chunk = [&](int ch, int p) {
        const int k0 = ch * 64;
        uint32_t sb = base + p * GBUF;
        #pragma unroll
        for (int it = 0; it < 4; ++it) {
            int idx = tid + it * 256;
            int r   = idx >> 3;
            int sg  = idx & 7;
            uint32_t d = (uint32_t)(r * SA + sg * 16);
            cp16(sb +          d, Ahi + (size_t)(rowBase + r) * DD + k0 + sg * 8);
            cp16(sb + 18432u + d, Alo + (size_t)(rowBase + r) * DD + k0 + sg * 8);
            cp16(sb + 36864u + d, Bhi + (size_t)(colBase + r) * DD + k0 + sg * 8);
            cp16(sb + 55296u + d, Blo + (size_t)(colBase + r) * DD + k0 + sg * 8);
        }
    };

    load_chunk(0, 0);
    cpcommit();

    for (int ch = 0; ch < 12; ++ch) {
        cpwait<0>();
        __syncthreads();
        if (ch < 11) { load_chunk(ch + 1, (ch + 1) & 1); cpcommit(); }

        const uint32_t uAh = base + (ch & 1) * GBUF;
        const uint32_t uAl = uAh + 18432u;
        const uint32_t uBh = uAh + 36864u;
        const uint32_t uBl = uAh + 55296u;

        #pragma unroll
        for (int kt = 0; kt < 4; ++kt) {
            const uint32_t ko = (uint32_t)kt * 32u;
            uint32_t afh[4][4], afl[4][4];
            #pragma unroll
            for (int mi = 0; mi < 4; ++mi) {
                uint32_t ao = (uint32_t)((wm + mi * 16) * SA) + ko;
                ldmat4(afh[mi], uAh + ao + laneA);
                ldmat4(afl[mi], uAl + ao + laneA);
            }
            uint32_t bh[2][4], bl[2][4];
            #pragma unroll
            for (int np = 0; np < 2; ++np) {
                uint32_t bo = (uint32_t)((wn + np * 16) * SA) + ko;
                ldmat4(bh[np], uBh + bo + laneB);
                ldmat4(bl[np], uBl + bo + laneB);
            }
            #pragma unroll
            for (int ni = 0; ni < 4; ++ni) {
                uint32_t b0h = bh[ni >> 1][(ni & 1) * 2];
                uint32_t b1h = bh[ni >> 1][(ni & 1) * 2 + 1];
                uint32_t b0l = bl[ni >> 1][(ni & 1) * 2];
                uint32_t b1l = bl[ni >> 1][(ni & 1) * 2 + 1];
                #pragma unroll
                for (int mi = 0; mi < 4; ++mi) {
                    mma16816(acc[mi][ni], afh[mi], b0h, b1h);
                    mma16816(acc[mi][ni], afl[mi], b0h, b1h);
                    mma16816(acc[mi][ni], afh[mi], b0l, b1l);
                }
            }
        }
    }

    #pragma unroll
    for (int mi = 0; mi < 4; ++mi) {
        int r0 = rowBase + wm + mi * 16 + g;
        int r1 = r0 + 8;
        #pragma unroll
        for (int ni = 0; ni < 4; ++ni) {
            int col = colBase + wn + ni * 8 + 2 * t;
            if (MODE == 0) {
                int h = col >> 6, dk = col & 63;
                int b0 = r0 >> 11, s0 = r0 & (SS - 1);
                int b1 = r1 >> 11, s1 = r1 & (SS - 1);
                size_t i0 = (((size_t)b0 * HH + h) * SS + s0) * DKK + dk;
                size_t i1 = (((size_t)b1 * HH + h) * SS + s1) * DKK + dk;
                const float sc = (z == 0) ? QSCALE : 1.0f;
                __half* dst = (z == 0) ? g_qh : (z == 1) ? g_kh : g_vh;
                *(uint32_t*)(dst + i0) = pkhf(acc[mi][ni][0] * sc, acc[mi][ni][1] * sc);
                *(uint32_t*)(dst + i1) = pkhf(acc[mi][ni][2] * sc, acc[mi][ni][3] * sc);
            } else {
                *(float2*)(outp + (size_t)r0 * DD + col) =
                    make_float2(acc[mi][ni][0], acc[mi][ni][1]);
                *(float2*)(outp + (size_t)r1 * DD + col) =
                    make_float2(acc[mi][ni][2], acc[mi][ni][3]);
            }
        }
    }
}

// ---------------------------------------------------------------------------
// Flash attention (all-fp16 single-pass): 128 thr (4 warps), 64 q/CTA,
// 64-key tiles.  S = qh·kh (1 MMA pass); softmax base-2; P fp16; O += P·V.
// Single __syncthreads per tile; cp.async double-buffered K/V.
// smem: Q 9216 + 2 buf x (K 9216 + V 9216) = 46080B -> 4 CTAs/SM.
// ---------------------------------------------------------------------------
#define FBUF 18432
#define FQ   9216

__global__ __launch_bounds__(128, 4)
void flash_tc()
{
    extern __shared__ char fsm[];
    const uint32_t base = smem_u32(fsm);
    const uint32_t uQ = base;

    const int tid  = threadIdx.x;
    const int warp = tid >> 5;
    const int lane = tid & 31;
    const int g    = lane >> 2;
    const int t    = lane & 3;
    const int b    = blockIdx.z;
    const int h    = blockIdx.y;
    const int qb   = (gridDim.x - 1) - blockIdx.x;   // heavy blocks first

    const size_t headOff = (size_t)(b * HH + h) * SS * DKK;

    const uint32_t laneA = (uint32_t)(((lane & 7) + ((lane >> 3) & 1) * 8) * SA
                                      + (lane >> 4) * 16);
    const uint32_t laneB = (uint32_t)(((lane & 7) + ((lane >> 4) & 1) * 8) * SA
                                      + ((lane >> 3) & 1) * 16);

    auto load_kv = [&](int kt_tile, int p) {
        uint32_t sb = base + FQ + p * FBUF;
        #pragma unroll
        for (int it = 0; it < 4; ++it) {
            int idx = tid + it * 128;        // 0..511
            int r   = idx >> 3;              // 0..63
            int sg  = idx & 7;
            size_t  s = headOff + (size_t)(kt_tile * 64 + r) * DKK + sg * 8;
            uint32_t d = (uint32_t)(r * SA + sg * 16);
            cp16(sb +         d, g_kh + s);
            cp16(sb + 9216u + d, g_vh + s);
        }
    };

    // stage Q
    #pragma unroll
    for (int it = 0; it < 4; ++it) {
        int idx = tid + it * 128;
        int r   = idx >> 3;
        int sg  = idx & 7;
        cp16(uQ + (uint32_t)(r * SA + sg * 16),
             g_qh + headOff + (size_t)(qb * 64 + r) * DKK + sg * 8);
    }
    load_kv(0, 0);
    cpcommit();

    float accO[8][4];
    #pragma unroll
    for (int d = 0; d < 8; ++d)
        #pragma unroll
        for (int r = 0; r < 4; ++r) accO[d][r] = 0.f;
    float m0 = -1e30f, m1 = -1e30f, l0 = 0.f, l1 = 0.f;

    const int qrow = warp * 16 + g;
    const int ntl  = qb + 1;

    for (int ch = 0; ch < ntl; ++ch) {
        cpwait<0>();
        __syncthreads();
        if (ch < ntl - 1) { load_kv(ch + 1, (ch + 1) & 1); cpcommit(); }

        const uint32_t uK = base + FQ + (ch & 1) * FBUF;
        const uint32_t uV = uK + 9216u;

        // ---- S = Q K^T (single fp16 pass) ----
        float sacc[8][4];
        #pragma unroll
        for (int nt = 0; nt < 8; ++nt)
            #pragma unroll
            for (int r = 0; r < 4; ++r) sacc[nt][r] = 0.f;

        #pragma unroll
        for (int kt = 0; kt < 4; ++kt) {
            const uint32_t ko = (uint32_t)kt * 32u;
            uint32_t qa[4];
            ldmat4(qa, uQ + (uint32_t)(warp * 16 * SA) + ko + laneA);
            uint32_t kf[4][4];
            #pragma unroll
            for (int np = 0; np < 4; ++np)
                ldmat4(kf[np], uK + (uint32_t)(np * 16 * SA) + ko + laneB);
            #pragma unroll
            for (int nt = 0; nt < 8; ++nt)
                mma16816h(sacc[nt], qa,
                          kf[nt >> 1][(nt & 1) * 2],
                          kf[nt >> 1][(nt & 1) * 2 + 1]);
        }

        // ---- causal mask on diagonal tile ----
        if (ch == qb) {
            #pragma unroll
            for (int nt = 0; nt < 8; ++nt) {
                int kc = nt * 8 + 2 * t;
                if (kc     > qrow)     sacc[nt][0] = -1e30f;
                if (kc + 1 > qrow)     sacc[nt][1] = -1e30f;
                if (kc     > qrow + 8) sacc[nt][2] = -1e30f;
                if (kc + 1 > qrow + 8) sacc[nt][3] = -1e30f;
            }
        }

        // ---- online softmax (base-2) ----
        float mx0 = -1e30f, mx1 = -1e30f;
        #pragma unroll
        for (int nt = 0; nt < 8; ++nt) {
            mx0 = fmaxf(mx0, fmaxf(sacc[nt][0], sacc[nt][1]));
            mx1 = fmaxf(mx1, fmaxf(sacc[nt][2], sacc[nt][3]));
        }
        mx0 = fmaxf(mx0, __shfl_xor_sync(0xffffffff, mx0, 1));
        mx0 = fmaxf(mx0, __shfl_xor_sync(0xffffffff, mx0, 2));
        mx1 = fmaxf(mx1, __shfl_xor_sync(0xffffffff, mx1, 1));
        mx1 = fmaxf(mx1, __shfl_xor_sync(0xffffffff, mx1, 2));
        float mn0 = fmaxf(m0, mx0), mn1 = fmaxf(m1, mx1);
        float cr0 = ex2f(m0 - mn0), cr1 = ex2f(m1 - mn1);
        m0 = mn0; m1 = mn1;
        l0 *= cr0; l1 *= cr1;
        #pragma unroll
        for (int d = 0; d < 8; ++d) {
            accO[d][0] *= cr0; accO[d][1] *= cr0;
            accO[d][2] *= cr1; accO[d][3] *= cr1;
        }

        // ---- P = 2^(S-m), fp16 A-fragments ----
        uint32_t pah[4][4];
        #pragma unroll
        for (int nt = 0; nt < 8; ++nt) {
            float p0 = ex2f(sacc[nt][0] - mn0);
            float p1 = ex2f(sacc[nt][1] - mn0);
            float p2 = ex2f(sacc[nt][2] - mn1);
            float p3 = ex2f(sacc[nt][3] - mn1);
            l0 += p0 + p1;
            l1 += p2 + p3;
            int kt = nt >> 1;
            if ((nt & 1) == 0) {
                pah[kt][0] = pkhf(p0, p1);
                pah[kt][1] = pkhf(p2, p3);
            } else {
                pah[kt][2] = pkhf(p0, p1);
                pah[kt][3] = pkhf(p2, p3);
            }
        }

        // ---- O += P V ----
        const int mat = lane >> 3;
        const int rr  = lane & 7;
        #pragma unroll
        for (int kt = 0; kt < 4; ++kt) {
            #pragma unroll
            for (int pr = 0; pr < 4; ++pr) {
                uint32_t off = (uint32_t)((kt * 16 + rr + (mat & 1) * 8) * SA)
                             + (uint32_t)((pr * 16 + (mat >> 1) * 8) * 2);
                uint32_t vv[4];
                ldmat4t(vv, uV + off);
                mma16816h(accO[2 * pr],     pah[kt], vv[0], vv[1]);
                mma16816h(accO[2 * pr + 1], pah[kt], vv[2], vv[3]);
            }
        }
    }

    // ---- finalize: write ctx as bf16 hi/lo ----
    l0 += __shfl_xor_sync(0xffffffff, l0, 1);
    l0 += __shfl_xor_sync(0xffffffff, l0, 2);
    l1 += __shfl_xor_sync(0xffffffff, l1, 1);
    l1 += __shfl_xor_sync(0xffffffff, l1, 2);
    float inv0 = 1.0f / l0, inv1 = 1.0f / l1;

    int q0 = qb * 64 + qrow;
    size_t base0 = ((size_t)b * SS + q0) * DD + h * DKK;
    size_t base1 = base0 + (size_t)8 * DD;
    #pragma unroll
    for (int d = 0; d < 8; ++d) {
        int col = d * 8 + 2 * t;
        uint32_t hi, lo;
        split2(accO[d][0] * inv0, accO[d][1] * inv0, hi, lo);
        *(uint32_t*)(g_chi + base0 + col) = hi;
        *(uint32_t*)(g_clo + base0 + col) = lo;
        split2(accO[d][2] * inv1, accO[d][3] * inv1, hi, lo);
        *(uint32_t*)(g_chi + base1 + col) = hi;
        *(uint32_t*)(g_clo + base1 + col) = lo;
    }
}

// ---------------------------------------------------------------------------
extern "C" void kernel_launch(void* const* d_in, const int* in_sizes, int n_in,
                              void* d_out, int out_size)
{
    (void)in_sizes; (void)n_in; (void)out_size;
    const float* Q  = (const float*)d_in[0];
    const float* K  = (const float*)d_in[1];
    const float* V  = (const float*)d_in[2];
    const float* Wq = (const float*)d_in[4];
    const float* Wk = (const float*)d_in[5];
    const float* Wv = (const float*)d_in[6];
    const float* Wo = (const float*)d_in[7];
    float* out = (float*)d_out;

    constexpr int GEMM_SMEM  = 2 * GBUF;      // 147456
    constexpr int FLASH_SMEM = FQ + 2 * FBUF; // 46080
    static bool attr_done = false;
    if (!attr_done) {
        cudaFuncSetAttribute(gemm_bf<0>,
                             cudaFuncAttributeMaxDynamicSharedMemorySize, GEMM_SMEM);
        cudaFuncSetAttribute(gemm_bf<1>,
                             cudaFuncAttributeMaxDynamicSharedMemorySize, GEMM_SMEM);
        cudaFuncSetAttribute(flash_tc,
                             cudaFuncAttributeMaxDynamicSharedMemorySize, FLASH_SMEM);
        attr_done = true;
    }

    conv_x<<<dim3(XN / 4 / 256, 1, 3), 256>>>(Q, K, V);
    conv_w<<<dim3(WN / 4 / 256, 1, 4), 256>>>(Wq, Wk, Wv, Wo);

    gemm_bf<0><<<dim3(DD / 128, (BB * SS) / 128, 3), 256, GEMM_SMEM>>>(nullptr);

    flash_tc<<<dim3(SS / 64, HH, BB), 128, FLASH_SMEM>>>();

    gemm_bf<1><<<dim3(DD / 128, (BB * SS) / 128, 1), 256, GEMM_SMEM>>>(out);
}